// round 5
// baseline (speedup 1.0000x reference)
#include <cuda_runtime.h>
#include <math.h>

#define B_    4
#define CIN   64
#define COUT  64
#define H_    128
#define W_    128
#define HW_   (H_*W_)
#define K2_   9

typedef unsigned long long u64;

__device__ __forceinline__ u64 pack2(float lo, float hi) {
    u64 r; asm("mov.b64 %0,{%1,%2};" : "=l"(r) : "f"(lo), "f"(hi)); return r;
}
__device__ __forceinline__ u64 bcast2(float v) {
    u64 r; asm("mov.b64 %0,{%1,%1};" : "=l"(r) : "f"(v)); return r;
}
__device__ __forceinline__ void unpack2(u64 v, float& lo, float& hi) {
    asm("mov.b64 {%0,%1},%2;" : "=f"(lo), "=f"(hi) : "l"(v));
}
__device__ __forceinline__ void ffma2(u64& acc, u64 a, u64 b) {
    asm("fma.rn.f32x2 %0,%1,%2,%0;" : "+l"(acc) : "l"(a), "l"(b));
}

// Scratch (allocation-free rule: __device__ globals)
__device__ float g_dy[B_*K2_*HW_];
__device__ float g_dx[B_*K2_*HW_];
__device__ float g_mask[B_*K2_*HW_];
__device__ float g_wt[K2_*CIN*COUT];   // [k][c][o]

// ---------------------------------------------------------------------------
// Offset/mask conv (+ fused weight transpose in extra blocks).
// om blocks (0..255): 2 rows x 128 cols, 128 threads; per thread the two
// vertically adjacent pixels are PACKED into one f32x2 accumulator.
// Weights staged in smem PRE-DUPLICATED as float2(w,w) so the FFMA2 broadcast
// operand is a single LDS.64. Channels in 4 chunks of 16 (31KB smem).
// ---------------------------------------------------------------------------
__global__ __launch_bounds__(128) void om_kernel(
    const float* __restrict__ x,
    const float* __restrict__ omw,
    const float* __restrict__ omb,
    const float* __restrict__ w)
{
    // ---- Fused weight transpose blocks ----
    if (blockIdx.x >= 256) {
        int tid = (blockIdx.x - 256) * 128 + threadIdx.x;
        for (int i = tid; i < COUT*CIN*K2_; i += 8*128) {
            int k = i % K2_;
            int c = (i / K2_) % CIN;
            int o = i / (K2_*CIN);
            g_wt[(k*CIN + c)*COUT + o] = w[i];
        }
        return;
    }

    __shared__ float2 ws2[16*9*27];   // [cl][j][o] duplicated, 31104 B
    int t  = threadIdx.x;
    int b  = blockIdx.x >> 6;
    int hp = blockIdx.x & 63;
    int h0 = hp * 2;
    int wcol = t;

    u64 acc2[27];
    #pragma unroll
    for (int o = 0; o < 27; o++) acc2[o] = 0ULL;

    for (int cb = 0; cb < 4; cb++) {
        __syncthreads();
        for (int i = t; i < 16*9*27; i += 128) {
            int o  = i % 27;
            int j  = (i / 27) % 9;
            int cl = i / 243;
            float v = omw[(o*CIN + (cb*16 + cl))*9 + j];
            ws2[i] = make_float2(v, v);
        }
        __syncthreads();

        for (int cl = 0; cl < 16; cl++) {
            const float* xc = x + (size_t)(b*CIN + cb*16 + cl) * HW_;
            float xv[4][3];
            #pragma unroll
            for (int rr = 0; rr < 4; rr++) {
                int row = h0 - 1 + rr;
                #pragma unroll
                for (int cc = 0; cc < 3; cc++) {
                    int col = wcol - 1 + cc;
                    bool ok = (row >= 0) && (row < H_) && (col >= 0) && (col < W_);
                    xv[rr][cc] = ok ? xc[row*W_ + col] : 0.f;
                }
            }
            const u64* wrow = (const u64*)(ws2 + cl*243);
            #pragma unroll
            for (int j = 0; j < 9; j++) {
                u64 a2 = pack2(xv[j/3][j%3], xv[j/3 + 1][j%3]);
                #pragma unroll
                for (int o = 0; o < 27; o++) {
                    ffma2(acc2[o], a2, wrow[j*27 + o]);
                }
            }
        }
    }

    // Route: dy[k]=om[2k], dx[k]=om[2k+1] (k<9), mask[k]=sigmoid(om[18+k])
    int pix = h0*W_ + wcol;
    #pragma unroll
    for (int o = 0; o < 27; o++) {
        float v0, v1;
        unpack2(acc2[o], v0, v1);
        v0 += omb[o]; v1 += omb[o];
        if (o < 18) {
            int kk = o >> 1;
            float* dst = (o & 1) ? g_dx : g_dy;
            int base = (b*K2_ + kk)*HW_;
            dst[base + pix]      = v0;
            dst[base + pix + W_] = v1;
        } else {
            int base = (b*K2_ + (o - 18))*HW_;
            g_mask[base + pix]      = 1.f / (1.f + expf(-v0));
            g_mask[base + pix + W_] = 1.f / (1.f + expf(-v1));
        }
    }
}

// ---------------------------------------------------------------------------
// Deformable conv main kernel.
// Block = (b, h) row: 128 pixels x 64 Cout. 128 threads.
// Per k: stage bilinear samples (x mask) into smem [64c][128p], then
// f32x2-packed register GEMM: acc packed over Cout pairs (weight pairs come
// aligned from ulonglong2 smem loads), samples broadcast-duplicated.
// smem = 16KB weights + 32KB samples = 48KB.
// ---------------------------------------------------------------------------
__global__ __launch_bounds__(128) void deform_kernel(
    const float* __restrict__ x,
    const float* __restrict__ bias,
    float* __restrict__ out)
{
    __shared__ float ws[CIN*COUT];    // [c][o]  16KB
    __shared__ float samp[CIN*W_];    // [c][p]  32KB

    int t  = threadIdx.x;
    int b  = blockIdx.x >> 7;
    int h  = blockIdx.x & 127;
    int ty = t >> 4;     // 0..7
    int tx = t & 15;     // 0..15
    const float* xb = x + (size_t)b*CIN*HW_;

    // acc2[i2][j]: i2 = 4 Cout-pairs, j = 8 pixels; each u64 = 2 fp32 accs
    u64 acc2[4][8];
    #pragma unroll
    for (int i = 0; i < 4; i++)
        #pragma unroll
        for (int j = 0; j < 8; j++)
            acc2[i][j] = 0ULL;

    int offidx = b*K2_*HW_ + h*W_ + t;

    for (int k = 0; k < K2_; k++) {
        __syncthreads();   // previous GEMM done before overwriting smem

        // Stage weight slice [c][o] for this k (float4 copies)
        {
            const float4* src = (const float4*)(g_wt + k*CIN*COUT);
            float4* dst = (float4*)ws;
            for (int i = t; i < CIN*COUT/4; i += 128)
                dst[i] = src[i];
        }

        // ---- Sampling: thread t handles pixel w = t ----
        float dyv = g_dy[offidx + k*HW_];
        float dxv = g_dx[offidx + k*HW_];
        float mk  = g_mask[offidx + k*HW_];
        float py = dyv + (float)(k/3 + h - 1);
        float px = dxv + (float)(k%3 + t - 1);
        float y0f = floorf(py), x0f = floorf(px);
        float wy = py - y0f,   wx = px - x0f;
        int y0 = (int)y0f, x0i = (int)x0f;
        int y1 = y0 + 1,   x1  = x0i + 1;
        float vy0 = (y0  >= 0 && y0  < H_) ? 1.f : 0.f;
        float vy1 = (y1  >= 0 && y1  < H_) ? 1.f : 0.f;
        float vx0 = (x0i >= 0 && x0i < W_) ? 1.f : 0.f;
        float vx1 = (x1  >= 0 && x1  < W_) ? 1.f : 0.f;
        float w00 = (1.f-wy)*(1.f-wx) * vy0*vx0 * mk;
        float w01 = (1.f-wy)*wx       * vy0*vx1 * mk;
        float w10 = wy*(1.f-wx)       * vy1*vx0 * mk;
        float w11 = wy*wx             * vy1*vx1 * mk;
        int iy0 = min(max(y0, 0), H_-1), iy1 = min(max(y1, 0), H_-1);
        int ix0 = min(max(x0i,0), W_-1), ix1 = min(max(x1, 0), W_-1);
        int i00 = iy0*W_ + ix0, i01 = iy0*W_ + ix1;
        int i10 = iy1*W_ + ix0, i11 = iy1*W_ + ix1;

        #pragma unroll 4
        for (int c = 0; c < CIN; c++) {
            const float* xc = xb + c*HW_;
            samp[c*W_ + t] = w00*xc[i00] + w01*xc[i01] + w10*xc[i10] + w11*xc[i11];
        }
        __syncthreads();

        // ---- GEMM: acc2 += Wpair[c][i2] * bcast(samp[c][p]) ----
        const ulonglong2* wsU = (const ulonglong2*)ws;   // 16 per c
        const float4* sp4 = (const float4*)samp;
        #pragma unroll 4
        for (int c = 0; c < CIN; c++) {
            ulonglong2 wA = wsU[c*16 + ty];       // o = ty*4 .. +3 (2 pairs)
            ulonglong2 wB = wsU[c*16 + 8 + ty];   // o = 32+ty*4 .. +3
            float4 s0 = sp4[c*32 + tx];           // p = tx*4 .. +3
            float4 s1 = sp4[c*32 + 16 + tx];      // p = 64+tx*4 .. +3
            u64 wp[4] = {wA.x, wA.y, wB.x, wB.y};
            u64 sb[8] = {bcast2(s0.x), bcast2(s0.y), bcast2(s0.z), bcast2(s0.w),
                         bcast2(s1.x), bcast2(s1.y), bcast2(s1.z), bcast2(s1.w)};
            #pragma unroll
            for (int i = 0; i < 4; i++)
                #pragma unroll
                for (int j = 0; j < 8; j++)
                    ffma2(acc2[i][j], wp[i], sb[j]);
        }
    }

    // Epilogue: unpack Cout pairs
    #pragma unroll
    for (int i = 0; i < 4; i++) {
        int oe = (i < 2) ? (ty*4 + 2*i) : (32 + ty*4 + 2*(i - 2));
        float b0 = bias[oe], b1 = bias[oe + 1];
        float* op0 = out + (size_t)(b*COUT + oe    )*HW_ + h*W_;
        float* op1 = out + (size_t)(b*COUT + oe + 1)*HW_ + h*W_;
        #pragma unroll
        for (int j = 0; j < 8; j++) {
            int p = (j < 4) ? (tx*4 + j) : (64 + tx*4 + (j - 4));
            float lo, hi;
            unpack2(acc2[i][j], lo, hi);
            op0[p] = lo + b0;
            op1[p] = hi + b1;
        }
    }
}

// ---------------------------------------------------------------------------
extern "C" void kernel_launch(void* const* d_in, const int* in_sizes, int n_in,
                              void* d_out, int out_size) {
    const float* x      = (const float*)d_in[0];
    const float* weight = (const float*)d_in[1];
    const float* bias   = (const float*)d_in[2];
    const float* omw    = (const float*)d_in[3];
    const float* omb    = (const float*)d_in[4];
    float* out = (float*)d_out;

    om_kernel<<<256 + 8, 128>>>(x, omw, omb, weight);
    deform_kernel<<<B_*H_, 128>>>(x, bias, out);
}

// round 16
// speedup vs baseline: 1.1470x; 1.1470x over previous
#include <cuda_runtime.h>
#include <math.h>

#define B_    4
#define CIN   64
#define COUT  64
#define H_    128
#define W_    128
#define HW_   (H_*W_)
#define K2_   9

typedef unsigned long long u64;

__device__ __forceinline__ u64 bcast2(float v) {
    u64 r; asm("mov.b64 %0,{%1,%1};" : "=l"(r) : "f"(v)); return r;
}
__device__ __forceinline__ void unpack2(u64 v, float& lo, float& hi) {
    asm("mov.b64 {%0,%1},%2;" : "=f"(lo), "=f"(hi) : "l"(v));
}
__device__ __forceinline__ void ffma2(u64& acc, u64 a, u64 b) {
    asm("fma.rn.f32x2 %0,%1,%2,%0;" : "+l"(acc) : "l"(a), "l"(b));
}

// Scratch (allocation-free rule: __device__ globals)
__device__ float g_dy[B_*K2_*HW_];
__device__ float g_dx[B_*K2_*HW_];
__device__ float g_mask[B_*K2_*HW_];
__device__ float g_wt[K2_*CIN*COUT];   // [k][c][o]

// ---------------------------------------------------------------------------
// Offset/mask conv — SCALAR (R1 form, known good) + fused weight transpose.
// Blocks 0..255: 2 rows x 128 cols, 128 threads, 2 vertical pixels/thread.
// ---------------------------------------------------------------------------
__global__ __launch_bounds__(128) void om_kernel(
    const float* __restrict__ x,
    const float* __restrict__ omw,
    const float* __restrict__ omb,
    const float* __restrict__ w)
{
    // ---- Fused weight transpose blocks ----
    if (blockIdx.x >= 256) {
        int tid = (blockIdx.x - 256) * 128 + threadIdx.x;
        for (int i = tid; i < COUT*CIN*K2_; i += 8*128) {
            int k = i % K2_;
            int c = (i / K2_) % CIN;
            int o = i / (K2_*CIN);
            g_wt[(k*CIN + c)*COUT + o] = w[i];
        }
        return;
    }

    __shared__ float ws[32*9*27];   // [c_local][j][o], 31104 B
    int t  = threadIdx.x;
    int b  = blockIdx.x >> 6;
    int hp = blockIdx.x & 63;
    int h0 = hp * 2;
    int wcol = t;

    float acc0[27], acc1[27];
    #pragma unroll
    for (int o = 0; o < 27; o++) { acc0[o] = 0.f; acc1[o] = 0.f; }

    for (int cb = 0; cb < 2; cb++) {
        __syncthreads();
        for (int i = t; i < 32*9*27; i += 128) {
            int o  = i % 27;
            int j  = (i / 27) % 9;
            int cl = i / 243;
            ws[i] = omw[(o*CIN + (cb*32 + cl))*9 + j];
        }
        __syncthreads();

        for (int cl = 0; cl < 32; cl++) {
            const float* xc = x + (size_t)(b*CIN + cb*32 + cl) * HW_;
            float xv[4][3];
            #pragma unroll
            for (int rr = 0; rr < 4; rr++) {
                int row = h0 - 1 + rr;
                #pragma unroll
                for (int cc = 0; cc < 3; cc++) {
                    int col = wcol - 1 + cc;
                    bool ok = (row >= 0) && (row < H_) && (col >= 0) && (col < W_);
                    xv[rr][cc] = ok ? xc[row*W_ + col] : 0.f;
                }
            }
            #pragma unroll
            for (int j = 0; j < 9; j++) {
                float a0 = xv[j/3    ][j%3];
                float a1 = xv[j/3 + 1][j%3];
                #pragma unroll
                for (int o = 0; o < 27; o++) {
                    float wv = ws[cl*243 + j*27 + o];
                    acc0[o] += wv * a0;
                    acc1[o] += wv * a1;
                }
            }
        }
    }

    // Route: dy[k]=om[2k], dx[k]=om[2k+1] (k<9), mask[k]=sigmoid(om[18+k])
    int pix = h0*W_ + wcol;
    #pragma unroll
    for (int o = 0; o < 27; o++) {
        float v0 = acc0[o] + omb[o];
        float v1 = acc1[o] + omb[o];
        if (o < 18) {
            int kk = o >> 1;
            float* dst = (o & 1) ? g_dx : g_dy;
            int base = (b*K2_ + kk)*HW_;
            dst[base + pix]      = v0;
            dst[base + pix + W_] = v1;
        } else {
            int base = (b*K2_ + (o - 18))*HW_;
            g_mask[base + pix]      = 1.f / (1.f + expf(-v0));
            g_mask[base + pix + W_] = 1.f / (1.f + expf(-v1));
        }
    }
}

// ---------------------------------------------------------------------------
// Deformable conv main kernel — 256 threads/block for 2x occupancy.
// Block = (b, h) row: 128 pixels x 64 Cout.
// Per k: 256 threads stage bilinear samples (each thread: 32 channels of one
// pixel), then f32x2 GEMM: thread tile 2 Cout-pairs x 8 pixels (16 u64 accs).
// smem = 16KB weights + 32KB samples = 48KB.
// ---------------------------------------------------------------------------
__global__ __launch_bounds__(256) void deform_kernel(
    const float* __restrict__ x,
    const float* __restrict__ bias,
    float* __restrict__ out)
{
    __shared__ float ws[CIN*COUT];    // [c][o]  16KB
    __shared__ float samp[CIN*W_];    // [c][p]  32KB

    int t  = threadIdx.x;
    int b  = blockIdx.x >> 7;
    int h  = blockIdx.x & 127;
    int ty = t >> 4;     // 0..15
    int tx = t & 15;     // 0..15
    const float* xb = x + (size_t)b*CIN*HW_;

    // acc2[i][j]: i = 2 Cout-pairs (o=2ty,2ty+1 and 32+2ty,+1), j = 8 pixels
    u64 acc2[2][8];
    #pragma unroll
    for (int i = 0; i < 2; i++)
        #pragma unroll
        for (int j = 0; j < 8; j++)
            acc2[i][j] = 0ULL;

    int p    = t & 127;          // sampling pixel
    int half = t >> 7;           // 0/1: channel half for sampling
    int offidx = b*K2_*HW_ + h*W_ + p;

    for (int k = 0; k < K2_; k++) {
        __syncthreads();   // previous GEMM done before overwriting smem

        // Stage weight slice [c][o] for this k (float4 copies)
        {
            const float4* src = (const float4*)(g_wt + k*CIN*COUT);
            float4* dst = (float4*)ws;
            for (int i = t; i < CIN*COUT/4; i += 256)
                dst[i] = src[i];
        }

        // ---- Sampling: two threads per pixel, 32 channels each ----
        float dyv = g_dy[offidx + k*HW_];
        float dxv = g_dx[offidx + k*HW_];
        float mk  = g_mask[offidx + k*HW_];
        float py = dyv + (float)(k/3 + h - 1);
        float px = dxv + (float)(k%3 + p - 1);
        float y0f = floorf(py), x0f = floorf(px);
        float wy = py - y0f,   wx = px - x0f;
        int y0 = (int)y0f, x0i = (int)x0f;
        int y1 = y0 + 1,   x1  = x0i + 1;
        float vy0 = (y0  >= 0 && y0  < H_) ? 1.f : 0.f;
        float vy1 = (y1  >= 0 && y1  < H_) ? 1.f : 0.f;
        float vx0 = (x0i >= 0 && x0i < W_) ? 1.f : 0.f;
        float vx1 = (x1  >= 0 && x1  < W_) ? 1.f : 0.f;
        float w00 = (1.f-wy)*(1.f-wx) * vy0*vx0 * mk;
        float w01 = (1.f-wy)*wx       * vy0*vx1 * mk;
        float w10 = wy*(1.f-wx)       * vy1*vx0 * mk;
        float w11 = wy*wx             * vy1*vx1 * mk;
        int iy0 = min(max(y0, 0), H_-1), iy1 = min(max(y1, 0), H_-1);
        int ix0 = min(max(x0i,0), W_-1), ix1 = min(max(x1, 0), W_-1);
        int i00 = iy0*W_ + ix0, i01 = iy0*W_ + ix1;
        int i10 = iy1*W_ + ix0, i11 = iy1*W_ + ix1;

        int c0 = half * 32;
        #pragma unroll 4
        for (int c = c0; c < c0 + 32; c++) {
            const float* xc = xb + c*HW_;
            samp[c*W_ + p] = w00*xc[i00] + w01*xc[i01] + w10*xc[i10] + w11*xc[i11];
        }
        __syncthreads();

        // ---- GEMM: acc2 += Wpair[c][i] * bcast(samp[c][p]) ----
        const u64*    wsU = (const u64*)ws;      // 32 pairs per c
        const float4* sp4 = (const float4*)samp;
        #pragma unroll 4
        for (int c = 0; c < CIN; c++) {
            u64 w0 = wsU[c*32 + ty];             // o = 2ty, 2ty+1
            u64 w1 = wsU[c*32 + 16 + ty];        // o = 32+2ty, +1
            float4 s0 = sp4[c*32 + tx];          // p = tx*4 .. +3
            float4 s1 = sp4[c*32 + 16 + tx];     // p = 64+tx*4 .. +3
            u64 sb[8] = {bcast2(s0.x), bcast2(s0.y), bcast2(s0.z), bcast2(s0.w),
                         bcast2(s1.x), bcast2(s1.y), bcast2(s1.z), bcast2(s1.w)};
            #pragma unroll
            for (int j = 0; j < 8; j++) {
                ffma2(acc2[0][j], w0, sb[j]);
                ffma2(acc2[1][j], w1, sb[j]);
            }
        }
    }

    // Epilogue: unpack Cout pairs
    #pragma unroll
    for (int i = 0; i < 2; i++) {
        int oe = (i == 0) ? (2*ty) : (32 + 2*ty);
        float b0 = bias[oe], b1 = bias[oe + 1];
        float* op0 = out + (size_t)(b*COUT + oe    )*HW_ + h*W_;
        float* op1 = out + (size_t)(b*COUT + oe + 1)*HW_ + h*W_;
        #pragma unroll
        for (int j = 0; j < 8; j++) {
            int pp = (j < 4) ? (tx*4 + j) : (64 + tx*4 + (j - 4));
            float lo, hi;
            unpack2(acc2[i][j], lo, hi);
            op0[pp] = lo + b0;
            op1[pp] = hi + b1;
        }
    }
}

// ---------------------------------------------------------------------------
extern "C" void kernel_launch(void* const* d_in, const int* in_sizes, int n_in,
                              void* d_out, int out_size) {
    const float* x      = (const float*)d_in[0];
    const float* weight = (const float*)d_in[1];
    const float* bias   = (const float*)d_in[2];
    const float* omw    = (const float*)d_in[3];
    const float* omb    = (const float*)d_in[4];
    float* out = (float*)d_out;

    om_kernel<<<256 + 8, 128>>>(x, omw, omb, weight);
    deform_kernel<<<B_*H_, 256>>>(x, bias, out);
}